// round 5
// baseline (speedup 1.0000x reference)
#include <cuda_runtime.h>
#include <math.h>

// ---------------- problem constants ----------------
#define BB   16
#define NN   512
#define HH   12
#define DKK  64
#define DD   768           // HH*DKK
#define BH   (BB*HH)       // 192
#define MROWS (BB*NN)      // 8192
#define KNN  153           // max(1, int(0.3*512))

// ---------------- scratch (device globals, no allocation) ----------------
__device__ float g_qkv[3 * BH * NN * DKK];     // [3][B][H][N][DK]  75.5 MB
__device__ float g_msg[MROWS * DD];            // [B*N, 768]
__device__ float g_y1 [MROWS * DD];
__device__ float g_preln[MROWS * DD];
__device__ unsigned char g_mask[BB * NN * NN]; // [B,N,N]

// =====================================================================
// kNN mask: per (b, n) row, bitonic-sort 512 keys ((f32bits<<32)|idx),
// take 153 smallest (ties broken by lower index — matches jax top_k).
// =====================================================================
__global__ void __launch_bounds__(256)
build_mask(const float* __restrict__ dist)
{
    int bid = blockIdx.x;
    int b = bid >> 9, n = bid & 511;
    unsigned char* mrow = g_mask + ((b << 9) + n) * NN;
    int tid = threadIdx.x;

    if (n == 0) {                       // super node row: all true
        for (int m = tid; m < NN; m += 256) mrow[m] = 1;
        return;
    }

    __shared__ unsigned long long key[512];
    for (int m = tid; m < NN; m += 256) {
        float v = (m == 0) ? 0.0f : dist[(b * 511 + (n - 1)) * 511 + (m - 1)];
        key[m] = ((unsigned long long)__float_as_uint(v) << 32) | (unsigned)m;
    }
    __syncthreads();

    // bitonic sort ascending
    for (int k = 2; k <= 512; k <<= 1) {
        for (int j = k >> 1; j > 0; j >>= 1) {
            for (int i = tid; i < 512; i += 256) {
                int ixj = i ^ j;
                if (ixj > i) {
                    bool up = ((i & k) == 0);
                    unsigned long long a = key[i], c = key[ixj];
                    if ((a > c) == up) { key[i] = c; key[ixj] = a; }
                }
            }
            __syncthreads();
        }
    }

    for (int m = tid; m < NN; m += 256) mrow[m] = 0;
    __syncthreads();
    for (int s = tid; s < KNN; s += 256)
        mrow[(int)(key[s] & 511u)] = 1;
    if (tid == 0) mrow[0] = 1;          // super node column always true
}

// =====================================================================
// Generic 64x64x16 fp32 GEMM  C = A @ W^T + bias, with mode epilogues.
//   mode 0: A = x,    z selects Q/K/V weights; store remapped to [3,B,H,N,DK]
//   mode 1: A = g_msg, silu epilogue -> g_y1
//   mode 2: A = g_y1,  + bias + residual(x) -> g_preln
// =====================================================================
__global__ void __launch_bounds__(256)
gemm_proj(const float* __restrict__ xin,
          const float* __restrict__ W0, const float* __restrict__ W1, const float* __restrict__ W2,
          const float* __restrict__ B0, const float* __restrict__ B1, const float* __restrict__ B2,
          int mode)
{
    const int K = DD;
    int bn = blockIdx.x, bm = blockIdx.y, z = blockIdx.z;
    const float* A  = (mode == 0) ? xin : (mode == 1) ? g_msg : g_y1;
    const float* W  = (z == 0) ? W0 : (z == 1) ? W1 : W2;
    const float* Bb = (z == 0) ? B0 : (z == 1) ? B1 : B2;

    __shared__ float As[16][64];
    __shared__ float Bs[16][64];

    int tid  = threadIdx.x;
    int lrow = tid >> 2;
    int lc4  = (tid & 3) << 2;
    const float* Ald = A + (bm * 64 + lrow) * K + lc4;
    const float* Wld = W + (bn * 64 + lrow) * K + lc4;

    int tx = tid & 15, ty = tid >> 4;
    float acc[4][4];
    #pragma unroll
    for (int i = 0; i < 4; i++)
        #pragma unroll
        for (int j = 0; j < 4; j++) acc[i][j] = 0.0f;

    for (int k0 = 0; k0 < K; k0 += 16) {
        float4 a4 = *(const float4*)(Ald + k0);
        float4 w4 = *(const float4*)(Wld + k0);
        As[lc4+0][lrow] = a4.x; As[lc4+1][lrow] = a4.y;
        As[lc4+2][lrow] = a4.z; As[lc4+3][lrow] = a4.w;
        Bs[lc4+0][lrow] = w4.x; Bs[lc4+1][lrow] = w4.y;
        Bs[lc4+2][lrow] = w4.z; Bs[lc4+3][lrow] = w4.w;
        __syncthreads();
        #pragma unroll
        for (int kk = 0; kk < 16; kk++) {
            float4 av = *(const float4*)&As[kk][ty << 2];
            float4 bv = *(const float4*)&Bs[kk][tx << 2];
            float a[4] = {av.x, av.y, av.z, av.w};
            float b[4] = {bv.x, bv.y, bv.z, bv.w};
            #pragma unroll
            for (int i = 0; i < 4; i++)
                #pragma unroll
                for (int j = 0; j < 4; j++)
                    acc[i][j] += a[i] * b[j];
        }
        __syncthreads();
    }

    int row0 = bm * 64 + (ty << 2);
    int col0 = bn * 64 + (tx << 2);
    #pragma unroll
    for (int i = 0; i < 4; i++) {
        int m = row0 + i;
        #pragma unroll
        for (int j = 0; j < 4; j++) {
            int n = col0 + j;
            float v = acc[i][j] + Bb[n];
            if (mode == 0) {
                int b = m >> 9, nn = m & 511, h = n >> 6, dk = n & 63;
                g_qkv[((((z * BB + b) * HH + h) * NN + nn) << 6) + dk] = v;
            } else if (mode == 1) {
                g_y1[m * DD + n] = v / (1.0f + expf(-v));
            } else {
                g_preln[m * DD + n] = v + xin[m * DD + n];
            }
        }
    }
}

// =====================================================================
// scores: per (b,h) S = Q K^T * 0.125, masked -> attn slice of d_out
// =====================================================================
__global__ void __launch_bounds__(256)
gemm_scores(float* __restrict__ attn)
{
    int bn = blockIdx.x, bm = blockIdx.y, z = blockIdx.z;   // z = b*12+h
    const float* Q  = g_qkv + z * (NN * DKK);
    const float* Km = g_qkv + BH * NN * DKK + z * (NN * DKK);

    __shared__ float As[16][64];
    __shared__ float Bs[16][64];

    int tid  = threadIdx.x;
    int lrow = tid >> 2;
    int lc4  = (tid & 3) << 2;
    const float* Ald = Q  + (bm * 64 + lrow) * DKK + lc4;
    const float* Bld = Km + (bn * 64 + lrow) * DKK + lc4;

    int tx = tid & 15, ty = tid >> 4;
    float acc[4][4];
    #pragma unroll
    for (int i = 0; i < 4; i++)
        #pragma unroll
        for (int j = 0; j < 4; j++) acc[i][j] = 0.0f;

    for (int k0 = 0; k0 < DKK; k0 += 16) {
        float4 a4 = *(const float4*)(Ald + k0);
        float4 b4 = *(const float4*)(Bld + k0);
        As[lc4+0][lrow] = a4.x; As[lc4+1][lrow] = a4.y;
        As[lc4+2][lrow] = a4.z; As[lc4+3][lrow] = a4.w;
        Bs[lc4+0][lrow] = b4.x; Bs[lc4+1][lrow] = b4.y;
        Bs[lc4+2][lrow] = b4.z; Bs[lc4+3][lrow] = b4.w;
        __syncthreads();
        #pragma unroll
        for (int kk = 0; kk < 16; kk++) {
            float4 av = *(const float4*)&As[kk][ty << 2];
            float4 bv = *(const float4*)&Bs[kk][tx << 2];
            float a[4] = {av.x, av.y, av.z, av.w};
            float b[4] = {bv.x, bv.y, bv.z, bv.w};
            #pragma unroll
            for (int i = 0; i < 4; i++)
                #pragma unroll
                for (int j = 0; j < 4; j++)
                    acc[i][j] += a[i] * b[j];
        }
        __syncthreads();
    }

    int b = z / HH;
    int row0 = bm * 64 + (ty << 2);
    int col0 = bn * 64 + (tx << 2);
    #pragma unroll
    for (int i = 0; i < 4; i++) {
        int n = row0 + i;
        const unsigned char* mr = g_mask + ((b << 9) + n) * NN;
        #pragma unroll
        for (int j = 0; j < 4; j++) {
            int mcol = col0 + j;
            float v = acc[i][j] * 0.125f;
            attn[(size_t)(z * NN + n) * NN + mcol] = mr[mcol] ? v : -1e12f;
        }
    }
}

// =====================================================================
// softmax over last dim (512) of attn, in place
// =====================================================================
__global__ void __launch_bounds__(128)
softmax512(float* __restrict__ attn)
{
    float* p = attn + (size_t)blockIdx.x * NN;
    int tid = threadIdx.x;
    float v[4];
    #pragma unroll
    for (int i = 0; i < 4; i++) v[i] = p[tid + (i << 7)];

    float mx = fmaxf(fmaxf(v[0], v[1]), fmaxf(v[2], v[3]));
    #pragma unroll
    for (int o = 16; o > 0; o >>= 1)
        mx = fmaxf(mx, __shfl_xor_sync(0xffffffffu, mx, o));
    __shared__ float sm[4], ss[4];
    int wp = tid >> 5, ln = tid & 31;
    if (ln == 0) sm[wp] = mx;
    __syncthreads();
    mx = fmaxf(fmaxf(sm[0], sm[1]), fmaxf(sm[2], sm[3]));

    float s = 0.0f;
    #pragma unroll
    for (int i = 0; i < 4; i++) { v[i] = expf(v[i] - mx); s += v[i]; }
    #pragma unroll
    for (int o = 16; o > 0; o >>= 1)
        s += __shfl_xor_sync(0xffffffffu, s, o);
    if (ln == 0) ss[wp] = s;
    __syncthreads();
    s = ss[0] + ss[1] + ss[2] + ss[3];
    float inv = 1.0f / s;
    #pragma unroll
    for (int i = 0; i < 4; i++) p[tid + (i << 7)] = v[i] * inv;
}

// =====================================================================
// msg = attn @ V  per (b,h): M=512, N=64, K=512; store [B,N,H*DK]
// =====================================================================
__global__ void __launch_bounds__(256)
gemm_msg(const float* __restrict__ attn)
{
    int bm = blockIdx.y, z = blockIdx.z;
    const float* A = attn + (size_t)z * (NN * NN);
    const float* V = g_qkv + 2 * BH * NN * DKK + z * (NN * DKK);

    __shared__ float As[16][64];
    __shared__ float Bs[16][64];

    int tid  = threadIdx.x;
    int lrow = tid >> 2;
    int lc4  = (tid & 3) << 2;
    const float* Ald = A + (bm * 64 + lrow) * NN + lc4;
    int brow = tid >> 4;
    int bc4  = (tid & 15) << 2;

    int tx = tid & 15, ty = tid >> 4;
    float acc[4][4];
    #pragma unroll
    for (int i = 0; i < 4; i++)
        #pragma unroll
        for (int j = 0; j < 4; j++) acc[i][j] = 0.0f;

    for (int k0 = 0; k0 < NN; k0 += 16) {
        float4 a4 = *(const float4*)(Ald + k0);
        float4 b4 = *(const float4*)(V + (k0 + brow) * DKK + bc4);
        As[lc4+0][lrow] = a4.x; As[lc4+1][lrow] = a4.y;
        As[lc4+2][lrow] = a4.z; As[lc4+3][lrow] = a4.w;
        *(float4*)&Bs[brow][bc4] = b4;
        __syncthreads();
        #pragma unroll
        for (int kk = 0; kk < 16; kk++) {
            float4 av = *(const float4*)&As[kk][ty << 2];
            float4 bv = *(const float4*)&Bs[kk][tx << 2];
            float a[4] = {av.x, av.y, av.z, av.w};
            float b[4] = {bv.x, bv.y, bv.z, bv.w};
            #pragma unroll
            for (int i = 0; i < 4; i++)
                #pragma unroll
                for (int j = 0; j < 4; j++)
                    acc[i][j] += a[i] * b[j];
        }
        __syncthreads();
    }

    int b = z / HH, h = z % HH;
    int row0 = bm * 64 + (ty << 2);
    int col0 = (tx << 2);
    #pragma unroll
    for (int i = 0; i < 4; i++) {
        int n = row0 + i;
        #pragma unroll
        for (int j = 0; j < 4; j++) {
            int dk = col0 + j;
            g_msg[(b * NN + n) * DD + h * DKK + dk] = acc[i][j];
        }
    }
}

// =====================================================================
// layernorm over 768, rows = B*N
// =====================================================================
__global__ void __launch_bounds__(256)
layernorm(const float* __restrict__ gam, const float* __restrict__ bet,
          float* __restrict__ out)
{
    int row = blockIdx.x;
    const float* p = g_preln + row * DD;
    int tid = threadIdx.x;
    float x0 = p[tid], x1 = p[tid + 256], x2 = p[tid + 512];

    __shared__ float red[256];
    red[tid] = x0 + x1 + x2;
    __syncthreads();
    for (int o = 128; o > 0; o >>= 1) {
        if (tid < o) red[tid] += red[tid + o];
        __syncthreads();
    }
    float mu = red[0] * (1.0f / 768.0f);
    __syncthreads();

    float d0 = x0 - mu, d1 = x1 - mu, d2 = x2 - mu;
    red[tid] = d0 * d0 + d1 * d1 + d2 * d2;
    __syncthreads();
    for (int o = 128; o > 0; o >>= 1) {
        if (tid < o) red[tid] += red[tid + o];
        __syncthreads();
    }
    float var = red[0] * (1.0f / 768.0f);
    float inv = 1.0f / sqrtf(var + 1e-6f);

    float* o = out + row * DD;
    o[tid]       = d0 * inv * gam[tid]       + bet[tid];
    o[tid + 256] = d1 * inv * gam[tid + 256] + bet[tid + 256];
    o[tid + 512] = d2 * inv * gam[tid + 512] + bet[tid + 512];
}

// =====================================================================
// launch
// =====================================================================
extern "C" void kernel_launch(void* const* d_in, const int* in_sizes, int n_in,
                              void* d_out, int out_size)
{
    const float* x    = (const float*)d_in[0];
    const float* dist = (const float*)d_in[1];
    const float* q_w  = (const float*)d_in[2];
    const float* q_b  = (const float*)d_in[3];
    const float* k_w  = (const float*)d_in[4];
    const float* k_b  = (const float*)d_in[5];
    const float* v_w  = (const float*)d_in[6];
    const float* v_b  = (const float*)d_in[7];
    const float* s1_w = (const float*)d_in[8];
    const float* s1_b = (const float*)d_in[9];
    const float* s2_w = (const float*)d_in[10];
    const float* s2_b = (const float*)d_in[11];
    const float* ln_g = (const float*)d_in[12];
    const float* ln_b = (const float*)d_in[13];

    float* out  = (float*)d_out;                    // [B,N,768]
    float* attn = out + (size_t)MROWS * DD;         // [B,H,1,N,N]

    // kNN mask
    build_mask<<<BB * NN, 256>>>(dist);

    // Q,K,V projections (z = 0/1/2)
    gemm_proj<<<dim3(DD / 64, MROWS / 64, 3), 256>>>(
        x, q_w, k_w, v_w, q_b, k_b, v_b, 0);

    // masked scores -> attn slice of d_out
    gemm_scores<<<dim3(NN / 64, NN / 64, BH), 256>>>(attn);

    // softmax in place
    softmax512<<<BH * NN, 128>>>(attn);

    // msg = attn @ V -> g_msg [B,N,768]
    gemm_msg<<<dim3(1, NN / 64, BH), 256>>>(attn);

    // s1 (silu) -> g_y1
    gemm_proj<<<dim3(DD / 64, MROWS / 64, 1), 256>>>(
        x, s1_w, s1_w, s1_w, s1_b, s1_b, s1_b, 1);

    // s2 + residual -> g_preln
    gemm_proj<<<dim3(DD / 64, MROWS / 64, 1), 256>>>(
        x, s2_w, s2_w, s2_w, s2_b, s2_b, s2_b, 2);

    // layernorm -> out
    layernorm<<<MROWS, 256>>>(ln_g, ln_b, out);
}